// round 8
// baseline (speedup 1.0000x reference)
#include <cuda_runtime.h>
#include <cuda_bf16.h>
#include <math.h>
#include <stdint.h>

#define NMAX    100000
#define EMBC    300
#define F4      75
#define KP      304         // padded K (19 k16 tiles)
#define U4W     76          // uint4s per W row: 304/4
#define NPAD    320
#define NGMAX   4096
#define NLAYER  5
#define EMAX    200000
#define NKT     19

// ---------------- device scratch ----------------
__device__ __align__(16) float    g_y   [(size_t)NMAX * EMBC];  // GEMM out Y
__device__ __align__(16) float    g_h   [(size_t)NMAX * EMBC];  // activations
__device__ __align__(16) unsigned g_wx  [NPAD * KP];            // g_wx[n*KP+k] = split(W[k][n])
__device__ float g_s[NMAX];
__device__ float g_colsum[EMBC];
__device__ float g_colsumsq[EMBC];
__device__ float g_scale[EMBC];
__device__ float g_shift[EMBC];
__device__ __align__(16) float g_hg[(size_t)NGMAX * EMBC];
__device__ __align__(16) float g_t [(size_t)NGMAX * 128];
__device__ int g_deg[NMAX];
__device__ int g_cursor[NMAX];
__device__ int g_row_ptr[NMAX + 1];
__device__ int g_csr_src[EMAX];
__device__ int g_csr_code[EMAX];

#define SEL_EXT  0
#define SEL_HG   2
#define SEL_T    4
__device__ __forceinline__ float* sel_ptr(int sel, float* ext)
{
    switch (sel) {
        case SEL_HG: return g_hg;
        case SEL_T:  return g_t;
        default:     return ext;
    }
}

// ---------------- split-bf16 helpers ----------------
__device__ __forceinline__ unsigned splitw(float v)
{
    __nv_bfloat16 h = __float2bfloat16(v);
    __nv_bfloat16 l = __float2bfloat16(v - __bfloat162float(h));
    return (unsigned)__bfloat16_as_ushort(h) | ((unsigned)__bfloat16_as_ushort(l) << 16);
}

// ---------------- smem helpers ----------------
__device__ __forceinline__ uint32_t smem_u32(const void* p)
{
    uint32_t a;
    asm("{ .reg .u64 t; cvta.to.shared.u64 t, %1; cvt.u32.u64 %0, t; }" : "=r"(a) : "l"(p));
    return a;
}
__device__ __forceinline__ void sts64(uint32_t addr, unsigned a, unsigned b)
{
    asm volatile("st.shared.v2.u32 [%0], {%1,%2};" :: "r"(addr), "r"(a), "r"(b) : "memory");
}
__device__ __forceinline__ uint32_t lds32(uint32_t addr)
{
    uint32_t v;
    asm volatile("ld.shared.b32 %0, [%1];" : "=r"(v) : "r"(addr));
    return v;
}
__device__ __forceinline__ void mma_bf16(float* c, const uint32_t* a, const uint32_t* b)
{
    asm volatile("mma.sync.aligned.m16n8k16.row.col.f32.bf16.bf16.f32 "
                 "{%0,%1,%2,%3}, {%4,%5,%6,%7}, {%8,%9}, {%0,%1,%2,%3};"
                 : "+f"(c[0]), "+f"(c[1]), "+f"(c[2]), "+f"(c[3])
                 : "r"(a[0]), "r"(a[1]), "r"(a[2]), "r"(a[3]), "r"(b[0]), "r"(b[1]));
}

// transform (optional BN+relu) + split fp32x4 -> hi/lo bf16 planes in smem
__device__ __forceinline__ void xsplit_sts(float4 x, float4 sc, float4 sh, int dobn,
                                           uint32_t hiaddr, uint32_t loaddr)
{
    if (dobn) {
        x.x = fmaxf(fmaf(x.x, sc.x, sh.x), 0.f);
        x.y = fmaxf(fmaf(x.y, sc.y, sh.y), 0.f);
        x.z = fmaxf(fmaf(x.z, sc.z, sh.z), 0.f);
        x.w = fmaxf(fmaf(x.w, sc.w, sh.w), 0.f);
    }
    unsigned w0 = splitw(x.x), w1 = splitw(x.y), w2 = splitw(x.z), w3 = splitw(x.w);
    sts64(hiaddr, __byte_perm(w0, w1, 0x5410), __byte_perm(w2, w3, 0x5410));
    sts64(loaddr, __byte_perm(w0, w1, 0x7632), __byte_perm(w2, w3, 0x7632));
}

// ================= CSR build =================
__global__ void k_zero2(int n)
{
    int i = blockIdx.x * blockDim.x + threadIdx.x;
    if (i < n) { g_deg[i] = 0; g_cursor[i] = 0; }
}
__global__ void k_count(const int* __restrict__ ei, int nE)
{
    int e = blockIdx.x * blockDim.x + threadIdx.x;
    if (e < nE) atomicAdd(&g_deg[ei[nE + e]], 1);
}
__global__ void k_scan(int n)
{
    __shared__ int sh[1024];
    int t = threadIdx.x;
    int chunk = (n + 1023) / 1024;
    int lo = t * chunk, hi = min(lo + chunk, n);
    int s = 0;
    for (int i = lo; i < hi; i++) s += g_deg[i];
    sh[t] = s;
    __syncthreads();
    for (int d = 1; d < 1024; d <<= 1) {
        int v = (t >= d) ? sh[t - d] : 0;
        __syncthreads();
        sh[t] += v;
        __syncthreads();
    }
    int run = sh[t] - s;
    for (int i = lo; i < hi; i++) { g_row_ptr[i] = run; run += g_deg[i]; }
    if (t == 1023) g_row_ptr[n] = run;
}
__global__ void k_fill(const int* __restrict__ ei, const int* __restrict__ et,
                       const int* __restrict__ ed, int nE)
{
    int e = blockIdx.x * blockDim.x + threadIdx.x;
    if (e >= nE) return;
    int c = ei[nE + e];
    int p = g_row_ptr[c] + atomicAdd(&g_cursor[c], 1);
    g_csr_src[p] = ei[e];
    g_csr_code[p] = et[e] * 3 + ed[e];
}

// ================= init: g_h = emb1[at] + emb2[ch] (fp32) =================
__global__ void k_init(const int* __restrict__ at, const int* __restrict__ ch,
                       const float* __restrict__ e1, const float* __restrict__ e2, int n)
{
    int idx = blockIdx.x * blockDim.x + threadIdx.x;
    if (idx >= n * F4) return;
    int i = idx / F4, c = idx % F4;
    float4 a = ((const float4*)e1)[(size_t)at[i] * F4 + c];
    float4 b = ((const float4*)e2)[(size_t)ch[i] * F4 + c];
    ((float4*)g_h)[idx] = make_float4(a.x + b.x, a.y + b.y, a.z + b.z, a.w + b.w);
}

// ================= per-layer: s[i] from CSR; zero col stats =================
__global__ void k_sconst(const float* __restrict__ ee1l, const float* __restrict__ ee2l, int n)
{
    int i = blockIdx.x * blockDim.x + threadIdx.x;
    if (i < n) {
        float base = ee1l[4] + ee2l[0];
        int p0 = g_row_ptr[i], p1 = g_row_ptr[i + 1];
        for (int p = p0; p < p1; p++) {
            int code = g_csr_code[p];
            base += ee1l[code / 3] + ee2l[code % 3];
        }
        g_s[i] = base;
    }
    if (i < EMBC) { g_colsum[i] = 0.f; g_colsumsq[i] = 0.f; }
}

// ================= BN scale/shift from stats =================
__global__ void k_mkscale(const float* __restrict__ gamma, const float* __restrict__ beta, int n)
{
    int i = threadIdx.x + blockIdx.x * blockDim.x;
    if (i >= EMBC) return;
    float inv_n = 1.f / (float)n;
    float mean = g_colsum[i] * inv_n;
    float var  = g_colsumsq[i] * inv_n - mean * mean;
    float sc = gamma[i] * rsqrtf(var + 1e-5f);
    g_scale[i] = sc;
    g_shift[i] = beta[i] - mean * sc;
}

// ================= W transpose + split (KP layout) =================
__global__ void k_wprep(const float* __restrict__ Wl)
{
    int idx = blockIdx.x * blockDim.x + threadIdx.x;
    if (idx >= NPAD * U4W) return;
    int nrow = idx / U4W, u = idx % U4W;
    unsigned w[4];
    #pragma unroll
    for (int j = 0; j < 4; j++) {
        int k = u * 4 + j;
        float v = (nrow < EMBC && k < EMBC) ? Wl[(size_t)k * EMBC + nrow] : 0.f;
        w[j] = splitw(v);
    }
    ((uint4*)g_wx)[idx] = make_uint4(w[0], w[1], w[2], w[3]);
}

// ================= HMMA split-bf16 GEMM: Y = T(h) @ W ======================
// T applied in A loader: mode=0 identity, mode=1 BN+relu via g_scale/g_shift.
// grid = (nb=5, mb); nb fastest for A-tile L2 reuse.
#define SBUF 18432

__global__ void __launch_bounds__(256)
k_gemm_mma(int M, int mode)
{
    __shared__ __align__(16) char smem[2 * SBUF];
    uint32_t sb = smem_u32(smem);
    int tid = threadIdx.x, lane = tid & 31, wid = tid >> 5;
    int wm = wid & 3, wn = wid >> 2;
    int m0 = blockIdx.y * 128, n0 = blockIdx.x * 64;
    const uint4* WG = (const uint4*)g_wx;

    int ar0 = tid >> 2, au = tid & 3;
    int br0 = tid >> 2;

    float acc[2][4][4] = {};
    float4 xa0, xa1, nxa0, nxa1;
    uint4 pb, npb;

    // prefetch + store k-tile 0
    {
        int k0 = au * 4;
        xa0 = make_float4(0.f, 0.f, 0.f, 0.f);
        xa1 = xa0;
        if (k0 < EMBC) {
            if (m0 + ar0      < M) xa0 = *(const float4*)&g_h[(size_t)(m0 + ar0)      * EMBC + k0];
            if (m0 + ar0 + 64 < M) xa1 = *(const float4*)&g_h[(size_t)(m0 + ar0 + 64) * EMBC + k0];
        }
        pb = WG[(size_t)(n0 + br0) * U4W + au];
        float4 sc = make_float4(1.f,1.f,1.f,1.f), sh = make_float4(0.f,0.f,0.f,0.f);
        int dobn = mode && (k0 < EMBC);
        if (dobn) { sc = *(const float4*)&g_scale[k0]; sh = *(const float4*)&g_shift[k0]; }
        xsplit_sts(xa0, sc, sh, dobn, sb +        ar0 * 48 + au * 8,        sb + 6144 + ar0 * 48 + au * 8);
        xsplit_sts(xa1, sc, sh, dobn, sb +        (ar0 + 64) * 48 + au * 8, sb + 6144 + (ar0 + 64) * 48 + au * 8);
        sts64(sb + 12288 + br0 * 48 + au * 8, __byte_perm(pb.x, pb.y, 0x5410), __byte_perm(pb.z, pb.w, 0x5410));
        sts64(sb + 15360 + br0 * 48 + au * 8, __byte_perm(pb.x, pb.y, 0x7632), __byte_perm(pb.z, pb.w, 0x7632));
    }
    __syncthreads();

    uint32_t aoff = (uint32_t)((wm * 32 + (lane >> 2)) * 48 + (lane & 3) * 4);
    uint32_t boff = (uint32_t)((wn * 32 + (lane >> 2)) * 48 + (lane & 3) * 4);

    for (int kt = 0; kt < NKT; kt++) {
        int b = kt & 1;
        if (kt < NKT - 1) {
            int k0 = (kt + 1) * 16 + au * 4;
            nxa0 = make_float4(0.f, 0.f, 0.f, 0.f);
            nxa1 = nxa0;
            if (k0 < EMBC) {
                if (m0 + ar0      < M) nxa0 = *(const float4*)&g_h[(size_t)(m0 + ar0)      * EMBC + k0];
                if (m0 + ar0 + 64 < M) nxa1 = *(const float4*)&g_h[(size_t)(m0 + ar0 + 64) * EMBC + k0];
            }
            npb = WG[(size_t)(n0 + br0) * U4W + (kt + 1) * 4 + au];
        }
        // ---- compute on buffer b ----
        {
            uint32_t base = sb + b * SBUF;
            uint32_t AH = base + aoff, AL = base + 6144 + aoff;
            uint32_t BH = base + 12288 + boff, BL = base + 15360 + boff;
            uint32_t af[2][2][4], bfr[4][2][2];
            #pragma unroll
            for (int mt = 0; mt < 2; mt++) {
                uint32_t r = AH + mt * 16 * 48;
                af[mt][0][0] = lds32(r);            af[mt][0][1] = lds32(r + 8 * 48);
                af[mt][0][2] = lds32(r + 16);       af[mt][0][3] = lds32(r + 8 * 48 + 16);
                uint32_t q = AL + mt * 16 * 48;
                af[mt][1][0] = lds32(q);            af[mt][1][1] = lds32(q + 8 * 48);
                af[mt][1][2] = lds32(q + 16);       af[mt][1][3] = lds32(q + 8 * 48 + 16);
            }
            #pragma unroll
            for (int nt = 0; nt < 4; nt++) {
                uint32_t r = BH + nt * 8 * 48;
                bfr[nt][0][0] = lds32(r);  bfr[nt][0][1] = lds32(r + 16);
                uint32_t q = BL + nt * 8 * 48;
                bfr[nt][1][0] = lds32(q);  bfr[nt][1][1] = lds32(q + 16);
            }
            #pragma unroll
            for (int mt = 0; mt < 2; mt++)
                #pragma unroll
                for (int nt = 0; nt < 4; nt++) {
                    mma_bf16(acc[mt][nt], af[mt][0], bfr[nt][0]);
                    mma_bf16(acc[mt][nt], af[mt][0], bfr[nt][1]);
                    mma_bf16(acc[mt][nt], af[mt][1], bfr[nt][0]);
                }
        }
        // store next k-tile into the other buffer
        if (kt < NKT - 1) {
            uint32_t base = sb + (b ^ 1) * SBUF;
            int k0 = (kt + 1) * 16 + au * 4;
            float4 sc = make_float4(1.f,1.f,1.f,1.f), sh = make_float4(0.f,0.f,0.f,0.f);
            int dobn = mode && (k0 < EMBC);
            if (dobn) { sc = *(const float4*)&g_scale[k0]; sh = *(const float4*)&g_shift[k0]; }
            xsplit_sts(nxa0, sc, sh, dobn, base +        ar0 * 48 + au * 8,        base + 6144 + ar0 * 48 + au * 8);
            xsplit_sts(nxa1, sc, sh, dobn, base +        (ar0 + 64) * 48 + au * 8, base + 6144 + (ar0 + 64) * 48 + au * 8);
            sts64(base + 12288 + br0 * 48 + au * 8, __byte_perm(npb.x, npb.y, 0x5410), __byte_perm(npb.z, npb.w, 0x5410));
            sts64(base + 15360 + br0 * 48 + au * 8, __byte_perm(npb.x, npb.y, 0x7632), __byte_perm(npb.z, npb.w, 0x7632));
        }
        __syncthreads();
    }

    // ---- epilogue: raw acc -> g_y ----
    #pragma unroll
    for (int mt = 0; mt < 2; mt++) {
        int row0 = m0 + wm * 32 + mt * 16 + (lane >> 2);
        int row1 = row0 + 8;
        #pragma unroll
        for (int nt = 0; nt < 4; nt++) {
            int col = n0 + wn * 32 + nt * 8 + (lane & 3) * 2;
            if (col < EMBC) {
                if (row0 < M) {
                    g_y[(size_t)row0 * EMBC + col]     = acc[mt][nt][0];
                    g_y[(size_t)row0 * EMBC + col + 1] = acc[mt][nt][1];
                }
                if (row1 < M) {
                    g_y[(size_t)row1 * EMBC + col]     = acc[mt][nt][2];
                    g_y[(size_t)row1 * EMBC + col + 1] = acc[mt][nt][3];
                }
            }
        }
    }
}

// ===== gather over Y: h[i] = Y[i] + sum_in Y[src] + b + s[i]; fused stats ===
// 300 threads/block; thread's column chunk c = tid % 75 is loop-invariant.
__global__ void __launch_bounds__(300)
k_gatherY(const float* __restrict__ bias, int n)
{
    __shared__ float red[300 * 8];
    int t = threadIdx.x;
    int c = t % 75, f = c * 4;
    float4 b4 = *(const float4*)&bias[f];
    float ls0 = 0.f, ls1 = 0.f, ls2 = 0.f, ls3 = 0.f;
    float lq0 = 0.f, lq1 = 0.f, lq2 = 0.f, lq3 = 0.f;

    int total = n * 75;
    int stride = gridDim.x * 300;
    for (int idx = blockIdx.x * 300 + t; idx < total; idx += stride) {
        int i = idx / 75;
        float4 v = *(const float4*)&g_y[(size_t)i * EMBC + f];
        float si = g_s[i];
        float v0 = v.x + b4.x + si, v1 = v.y + b4.y + si;
        float v2 = v.z + b4.z + si, v3 = v.w + b4.w + si;
        int p0 = g_row_ptr[i], p1 = g_row_ptr[i + 1];
        for (int p = p0; p < p1; p++) {
            float4 y = *(const float4*)&g_y[(size_t)g_csr_src[p] * EMBC + f];
            v0 += y.x; v1 += y.y; v2 += y.z; v3 += y.w;
        }
        *(float4*)&g_h[(size_t)i * EMBC + f] = make_float4(v0, v1, v2, v3);
        ls0 += v0; ls1 += v1; ls2 += v2; ls3 += v3;
        lq0 += v0 * v0; lq1 += v1 * v1; lq2 += v2 * v2; lq3 += v3 * v3;
    }
    red[t * 8 + 0] = ls0; red[t * 8 + 1] = ls1; red[t * 8 + 2] = ls2; red[t * 8 + 3] = ls3;
    red[t * 8 + 4] = lq0; red[t * 8 + 5] = lq1; red[t * 8 + 6] = lq2; red[t * 8 + 7] = lq3;
    __syncthreads();
    if (t < 75) {
        #pragma unroll
        for (int j = 0; j < 8; j++) {
            float s = red[t * 8 + j] + red[(t + 75) * 8 + j]
                    + red[(t + 150) * 8 + j] + red[(t + 225) * 8 + j];
            int col = t * 4 + (j & 3);
            if (j < 4) atomicAdd(&g_colsum[col], s);
            else       atomicAdd(&g_colsumsq[col], s);
        }
    }
}

// ================= final-layer norm (no relu), in place ================
__global__ void k_normfinal(int n)
{
    int idx = blockIdx.x * blockDim.x + threadIdx.x;
    if (idx >= n * F4) return;
    int f = (idx % F4) * 4;
    float4 sc = *(const float4*)&g_scale[f];
    float4 sh = *(const float4*)&g_shift[f];
    float4 x = ((float4*)g_h)[idx];
    ((float4*)g_h)[idx] = make_float4(sc.x * x.x + sh.x, sc.y * x.y + sh.y,
                                      sc.z * x.z + sh.z, sc.w * x.w + sh.w);
}

// ================= mean pool =================
__device__ __forceinline__ int lower_bound_i(const int* a, int n, int v)
{
    int lo = 0, hi = n;
    while (lo < hi) { int m = (lo + hi) >> 1; if (a[m] < v) lo = m + 1; else hi = m; }
    return lo;
}
__global__ void k_pool(const int* __restrict__ batch, int n)
{
    int g = blockIdx.x;
    int start = lower_bound_i(batch, n, g);
    int end   = lower_bound_i(batch, n, g + 1);
    int f = threadIdx.x;
    if (f >= EMBC) return;
    float s = 0.f;
    for (int i = start; i < end; i++)
        s += g_h[(size_t)i * EMBC + f];
    g_hg[(size_t)g * EMBC + f] = s / fmaxf((float)(end - start), 1.f);
}

// ================= SIMT sgemm for head =================
template<int EPI>
__global__ __launch_bounds__(256)
void k_sgemm(int a_sel, float* a_ext, const float* __restrict__ B,
             int c_sel, float* c_ext, int M, int N, int K,
             const float* __restrict__ bias)
{
    const float* A = sel_ptr(a_sel, a_ext);
    float*       C = sel_ptr(c_sel, c_ext);
    __shared__ __align__(16) float As[16][64];
    __shared__ __align__(16) float Bs[16][64];
    int tid = threadIdx.x;
    int tx = tid & 15, ty = tid >> 4;
    int m0 = blockIdx.x * 64, n0 = blockIdx.y * 64;
    int am = tid >> 2, ak4 = tid & 3;
    int bk = tid >> 4, bn4 = tid & 15;
    float acc[4][4] = {};
    for (int kt = 0; kt < K; kt += 16) {
        float4 av = make_float4(0.f, 0.f, 0.f, 0.f);
        int arow = m0 + am, acol = kt + ak4 * 4;
        if (arow < M && acol + 4 <= K)
            av = *(const float4*)(A + (size_t)arow * K + acol);
        As[ak4 * 4 + 0][am] = av.x;
        As[ak4 * 4 + 1][am] = av.y;
        As[ak4 * 4 + 2][am] = av.z;
        As[ak4 * 4 + 3][am] = av.w;
        float4 bv = make_float4(0.f, 0.f, 0.f, 0.f);
        int brow = kt + bk, bcol = n0 + bn4 * 4;
        if (brow < K && bcol + 4 <= N)
            bv = *(const float4*)(B + (size_t)brow * N + bcol);
        *(float4*)&Bs[bk][bn4 * 4] = bv;
        __syncthreads();
        #pragma unroll
        for (int k = 0; k < 16; k++) {
            float4 a4 = *(const float4*)&As[k][ty * 4];
            float4 b4 = *(const float4*)&Bs[k][tx * 4];
            float ar[4] = {a4.x, a4.y, a4.z, a4.w};
            float br[4] = {b4.x, b4.y, b4.z, b4.w};
            #pragma unroll
            for (int i = 0; i < 4; i++)
                #pragma unroll
                for (int j = 0; j < 4; j++)
                    acc[i][j] += ar[i] * br[j];
        }
        __syncthreads();
    }
    float bb[4];
    #pragma unroll
    for (int j = 0; j < 4; j++) {
        int col = n0 + tx * 4 + j;
        bb[j] = (col < N) ? bias[col] : 0.f;
    }
    #pragma unroll
    for (int i = 0; i < 4; i++) {
        int row = m0 + ty * 4 + i;
        if (row >= M) continue;
        #pragma unroll
        for (int j = 0; j < 4; j++) {
            int col = n0 + tx * 4 + j;
            if (col >= N) continue;
            float v = acc[i][j] + bb[j];
            if (EPI == 1)
                v = (v > 0.f) ? v + log1pf(expf(-v)) : log1pf(expf(v));
            C[(size_t)row * N + col] = v;
        }
    }
}

__global__ void k_pred(const float* __restrict__ W2, const float* __restrict__ b2,
                       float* __restrict__ out)
{
    int g = blockIdx.x;
    int w = threadIdx.x >> 5;
    int lane = threadIdx.x & 31;
    float s = 0.f;
    #pragma unroll
    for (int q = 0; q < 4; q++) {
        int i = lane * 4 + q;
        s += g_t[(size_t)g * 128 + i] * W2[i * 2 + w];
    }
    #pragma unroll
    for (int o = 16; o > 0; o >>= 1) s += __shfl_xor_sync(0xffffffffu, s, o);
    if (lane == 0) out[g * 2 + w] = s + b2[w];
}

// ======================================================================
extern "C" void kernel_launch(void* const* d_in, const int* in_sizes, int n_in,
                              void* d_out, int out_size)
{
    const int*   atom_type = (const int*)d_in[0];
    const int*   chirality = (const int*)d_in[1];
    const int*   edge_index= (const int*)d_in[2];
    const int*   edge_type = (const int*)d_in[3];
    const int*   edge_dir  = (const int*)d_in[4];
    const int*   batch     = (const int*)d_in[5];
    const float* atom_emb1 = (const float*)d_in[6];
    const float* atom_emb2 = (const float*)d_in[7];
    const float* W         = (const float*)d_in[8];
    const float* b         = (const float*)d_in[9];
    const float* ee1       = (const float*)d_in[10];
    const float* ee2       = (const float*)d_in[11];
    const float* bn_gamma  = (const float*)d_in[12];
    const float* bn_beta   = (const float*)d_in[13];
    const float* feat_W    = (const float*)d_in[14];
    const float* feat_b    = (const float*)d_in[15];
    const float* head_W1   = (const float*)d_in[16];
    const float* head_b1   = (const float*)d_in[17];
    const float* head_W2   = (const float*)d_in[18];
    const float* head_b2   = (const float*)d_in[19];

    int N  = in_sizes[0];
    int E  = in_sizes[3];
    int NG = out_size / (256 + 2);

    float* out_f = (float*)d_out;
    float* hf    = out_f;
    float* pred  = out_f + (size_t)NG * 256;

    // CSR build
    k_zero2<<<(N + 255) / 256, 256>>>(N);
    k_count<<<(E + 255) / 256, 256>>>(edge_index, E);
    k_scan<<<1, 1024>>>(N);
    k_fill<<<(E + 255) / 256, 256>>>(edge_index, edge_type, edge_dir, E);

    // embedding init (fp32 h)
    k_init<<<(N * F4 + 255) / 256, 256>>>(atom_type, chirality, atom_emb1, atom_emb2, N);

    dim3 ggrid(NPAD / 64, (N + 127) / 128);   // nb fastest -> A-tile L2 reuse
    for (int l = 0; l < NLAYER; l++) {
        const float* Wl   = W  + (size_t)l * EMBC * EMBC;
        const float* bl   = b  + (size_t)l * EMBC;
        const float* ee1l = ee1 + l * 5;
        const float* ee2l = ee2 + l * 3;

        if (l > 0)
            k_mkscale<<<2, 160>>>(bn_gamma + (l - 1) * EMBC, bn_beta + (l - 1) * EMBC, N);
        k_sconst<<<(N + 255) / 256, 256>>>(ee1l, ee2l, N);
        k_wprep<<<(NPAD * U4W + 255) / 256, 256>>>(Wl);
        k_gemm_mma<<<ggrid, 256>>>(N, l > 0 ? 1 : 0);
        k_gatherY<<<240, 300>>>(bl, N);
    }

    k_mkscale<<<2, 160>>>(bn_gamma + (NLAYER - 1) * EMBC, bn_beta + (NLAYER - 1) * EMBC, N);
    k_normfinal<<<(N * F4 + 255) / 256, 256>>>(N);

    k_pool<<<NG, 320>>>(batch, N);
    {
        dim3 grid((NG + 63) / 64, (256 + 63) / 64);
        k_sgemm<0><<<grid, 256>>>(SEL_HG, nullptr, feat_W, SEL_EXT, hf,
                                  NG, 256, EMBC, feat_b);
    }
    {
        dim3 grid((NG + 63) / 64, (128 + 63) / 64);
        k_sgemm<1><<<grid, 256>>>(SEL_EXT, hf, head_W1, SEL_T, nullptr,
                                  NG, 128, 256, head_b1);
    }
    k_pred<<<NG, 64>>>(head_W2, head_b2, pred);
}

// round 9
// speedup vs baseline: 1.2803x; 1.2803x over previous
#include <cuda_runtime.h>
#include <cuda_bf16.h>
#include <math.h>
#include <stdint.h>

#define NMAX    100000
#define EMBC    300
#define F4      75
#define KP      304         // padded K: 19 k16 tiles
#define U4A     76          // uint4s per packed A row: 304/4
#define NPAD    320         // padded N (output cols)
#define NKT     19
#define NGMAX   4096
#define NLAYER  5
#define EMAX    200000

// ---------------- device scratch ----------------
__device__ __align__(16) unsigned g_aggx[(size_t)NMAX * KP];    // packed (hi|lo<<16) bf16
__device__ __align__(16) float    g_h   [(size_t)NMAX * EMBC];  // fp32 activations
__device__ __align__(16) unsigned g_wx  [NPAD * KP];            // g_wx[n*KP+k] = split(W[k][n])
__device__ float g_s[NMAX];
__device__ float g_colsum[EMBC];
__device__ float g_colsumsq[EMBC];
__device__ float g_scale[EMBC];
__device__ float g_shift[EMBC];
__device__ __align__(16) float g_hg[(size_t)NGMAX * EMBC];
__device__ __align__(16) float g_t [(size_t)NGMAX * 128];
__device__ int g_deg[NMAX];
__device__ int g_cursor[NMAX];
__device__ int g_row_ptr[NMAX + 1];
__device__ int g_csr_src[EMAX];
__device__ int g_csr_code[EMAX];

#define SEL_EXT  0
#define SEL_HG   2
#define SEL_T    4
__device__ __forceinline__ float* sel_ptr(int sel, float* ext)
{
    switch (sel) {
        case SEL_HG: return g_hg;
        case SEL_T:  return g_t;
        default:     return ext;
    }
}

// ---------------- split-bf16 helpers ----------------
__device__ __forceinline__ unsigned splitw(float v)
{
    __nv_bfloat16 h = __float2bfloat16(v);
    __nv_bfloat16 l = __float2bfloat16(v - __bfloat162float(h));
    return (unsigned)__bfloat16_as_ushort(h) | ((unsigned)__bfloat16_as_ushort(l) << 16);
}

// ---------------- smem helpers ----------------
__device__ __forceinline__ uint32_t smem_u32(const void* p)
{
    uint32_t a;
    asm("{ .reg .u64 t; cvta.to.shared.u64 t, %1; cvt.u32.u64 %0, t; }" : "=r"(a) : "l"(p));
    return a;
}
__device__ __forceinline__ void sts64(uint32_t addr, unsigned a, unsigned b)
{
    asm volatile("st.shared.v2.u32 [%0], {%1,%2};" :: "r"(addr), "r"(a), "r"(b) : "memory");
}
__device__ __forceinline__ uint32_t lds32(uint32_t addr)
{
    uint32_t v;
    asm volatile("ld.shared.b32 %0, [%1];" : "=r"(v) : "r"(addr));
    return v;
}
__device__ __forceinline__ void mma_bf16(float* c, const uint32_t* a, const uint32_t* b)
{
    asm volatile("mma.sync.aligned.m16n8k16.row.col.f32.bf16.bf16.f32 "
                 "{%0,%1,%2,%3}, {%4,%5,%6,%7}, {%8,%9}, {%0,%1,%2,%3};"
                 : "+f"(c[0]), "+f"(c[1]), "+f"(c[2]), "+f"(c[3])
                 : "r"(a[0]), "r"(a[1]), "r"(a[2]), "r"(a[3]), "r"(b[0]), "r"(b[1]));
}

// ================= CSR build =================
__global__ void k_zero2(int n)
{
    int i = blockIdx.x * blockDim.x + threadIdx.x;
    if (i < n) { g_deg[i] = 0; g_cursor[i] = 0; }
}
__global__ void k_count(const int* __restrict__ ei, int nE)
{
    int e = blockIdx.x * blockDim.x + threadIdx.x;
    if (e < nE) atomicAdd(&g_deg[ei[nE + e]], 1);
}
__global__ void k_scan(int n)
{
    __shared__ int sh[1024];
    int t = threadIdx.x;
    int chunk = (n + 1023) / 1024;
    int lo = t * chunk, hi = min(lo + chunk, n);
    int s = 0;
    for (int i = lo; i < hi; i++) s += g_deg[i];
    sh[t] = s;
    __syncthreads();
    for (int d = 1; d < 1024; d <<= 1) {
        int v = (t >= d) ? sh[t - d] : 0;
        __syncthreads();
        sh[t] += v;
        __syncthreads();
    }
    int run = sh[t] - s;
    for (int i = lo; i < hi; i++) { g_row_ptr[i] = run; run += g_deg[i]; }
    if (t == 1023) g_row_ptr[n] = run;
}
__global__ void k_fill(const int* __restrict__ ei, const int* __restrict__ et,
                       const int* __restrict__ ed, int nE)
{
    int e = blockIdx.x * blockDim.x + threadIdx.x;
    if (e >= nE) return;
    int c = ei[nE + e];
    int p = g_row_ptr[c] + atomicAdd(&g_cursor[c], 1);
    g_csr_src[p] = ei[e];
    g_csr_code[p] = et[e] * 3 + ed[e];
}

// ================= init: g_h = emb1[at] + emb2[ch] (fp32) =================
__global__ void k_init(const int* __restrict__ at, const int* __restrict__ ch,
                       const float* __restrict__ e1, const float* __restrict__ e2, int n)
{
    int idx = blockIdx.x * blockDim.x + threadIdx.x;
    if (idx >= n * F4) return;
    int i = idx / F4, c = idx % F4;
    float4 a = ((const float4*)e1)[(size_t)at[i] * F4 + c];
    float4 b = ((const float4*)e2)[(size_t)ch[i] * F4 + c];
    ((float4*)g_h)[idx] = make_float4(a.x + b.x, a.y + b.y, a.z + b.z, a.w + b.w);
}

// ================= per-layer: s[i] from CSR; zero col stats =================
__global__ void k_sconst(const float* __restrict__ ee1l, const float* __restrict__ ee2l, int n)
{
    int i = blockIdx.x * blockDim.x + threadIdx.x;
    if (i < n) {
        float base = ee1l[4] + ee2l[0];
        int p0 = g_row_ptr[i], p1 = g_row_ptr[i + 1];
        for (int p = p0; p < p1; p++) {
            int code = g_csr_code[p];
            base += ee1l[code / 3] + ee2l[code % 3];
        }
        g_s[i] = base;
    }
    if (i < EMBC) { g_colsum[i] = 0.f; g_colsumsq[i] = 0.f; }
}

// ================= BN scale/shift from stats =================
__global__ void k_mkscale(const float* __restrict__ gamma, const float* __restrict__ beta, int n)
{
    int i = threadIdx.x + blockIdx.x * blockDim.x;
    if (i >= EMBC) return;
    float inv_n = 1.f / (float)n;
    float mean = g_colsum[i] * inv_n;
    float var  = g_colsumsq[i] * inv_n - mean * mean;
    float sc = gamma[i] * rsqrtf(var + 1e-5f);
    g_scale[i] = sc;
    g_shift[i] = beta[i] - mean * sc;
}

// ================= W transpose + split =================
__global__ void k_wprep(const float* __restrict__ Wl)
{
    int idx = blockIdx.x * blockDim.x + threadIdx.x;
    if (idx >= NPAD * U4A) return;
    int nrow = idx / U4A, u = idx % U4A;
    unsigned w[4];
    #pragma unroll
    for (int j = 0; j < 4; j++) {
        int k = u * 4 + j;
        float v = (nrow < EMBC && k < EMBC) ? Wl[(size_t)k * EMBC + nrow] : 0.f;
        w[j] = splitw(v);
    }
    ((uint4*)g_wx)[idx] = make_uint4(w[0], w[1], w[2], w[3]);
}

// ======= fused gather: aggx[i] = split( T(h[i]) + sum_in T(h[src]) ) ========
// mode 0: T = identity (layer 0). mode 1: T(x) = max(scale*x+shift, 0).
__global__ void k_gather2(int n, int mode)
{
    int idx = blockIdx.x * blockDim.x + threadIdx.x;
    if (idx >= n * U4A) return;
    int i = idx / U4A, c = idx % U4A;
    if (c >= F4) { ((uint4*)g_aggx)[idx] = make_uint4(0, 0, 0, 0); return; }
    int f = c * 4;
    float4 sc = make_float4(1.f, 1.f, 1.f, 1.f);
    float4 sh = make_float4(0.f, 0.f, 0.f, 0.f);
    if (mode) {
        sc = *(const float4*)&g_scale[f];
        sh = *(const float4*)&g_shift[f];
    }
    float4 x = *(const float4*)&g_h[(size_t)i * EMBC + f];
    float v0, v1, v2, v3;
    if (mode) {
        v0 = fmaxf(fmaf(x.x, sc.x, sh.x), 0.f); v1 = fmaxf(fmaf(x.y, sc.y, sh.y), 0.f);
        v2 = fmaxf(fmaf(x.z, sc.z, sh.z), 0.f); v3 = fmaxf(fmaf(x.w, sc.w, sh.w), 0.f);
    } else { v0 = x.x; v1 = x.y; v2 = x.z; v3 = x.w; }
    int p0 = g_row_ptr[i], p1 = g_row_ptr[i + 1];
    for (int p = p0; p < p1; p++) {
        float4 y = *(const float4*)&g_h[(size_t)g_csr_src[p] * EMBC + f];
        if (mode) {
            v0 += fmaxf(fmaf(y.x, sc.x, sh.x), 0.f); v1 += fmaxf(fmaf(y.y, sc.y, sh.y), 0.f);
            v2 += fmaxf(fmaf(y.z, sc.z, sh.z), 0.f); v3 += fmaxf(fmaf(y.w, sc.w, sh.w), 0.f);
        } else { v0 += y.x; v1 += y.y; v2 += y.z; v3 += y.w; }
    }
    uint4 o;
    o.x = splitw(v0); o.y = splitw(v1); o.z = splitw(v2); o.w = splitw(v3);
    ((uint4*)g_aggx)[idx] = o;
}

// ================= HMMA split-bf16 GEMM + fused column stats ================
// grid = (nb=5, mb); nb fastest so the 5 CTAs sharing an A-tile co-run (L2 reuse)
#define SBUF 18432

__global__ void __launch_bounds__(256)
k_gemm_mma(const float* __restrict__ bias, int M)
{
    __shared__ __align__(16) char smem[2 * SBUF];
    __shared__ float s_sum[64], s_sq[64];
    uint32_t sb = smem_u32(smem);
    int tid = threadIdx.x, lane = tid & 31, wid = tid >> 5;
    int wm = wid & 3, wn = wid >> 2;
    int m0 = blockIdx.y * 128, n0 = blockIdx.x * 64;
    const uint4* AG = (const uint4*)g_aggx;
    const uint4* WG = (const uint4*)g_wx;

    int ar0 = tid >> 2, au = tid & 3;
    int br0 = tid >> 2;

    float acc[2][4][4] = {};
    uint4 pa0, pa1, pb;

    pa0 = (m0 + ar0      < M) ? AG[(size_t)(m0 + ar0)      * U4A + au] : make_uint4(0,0,0,0);
    pa1 = (m0 + ar0 + 64 < M) ? AG[(size_t)(m0 + ar0 + 64) * U4A + au] : make_uint4(0,0,0,0);
    pb  = WG[(size_t)(n0 + br0) * U4A + au];
    {
        uint32_t base = sb;
        sts64(base +         ar0 * 48 + au * 8,        __byte_perm(pa0.x, pa0.y, 0x5410), __byte_perm(pa0.z, pa0.w, 0x5410));
        sts64(base + 6144 +  ar0 * 48 + au * 8,        __byte_perm(pa0.x, pa0.y, 0x7632), __byte_perm(pa0.z, pa0.w, 0x7632));
        sts64(base +         (ar0 + 64) * 48 + au * 8, __byte_perm(pa1.x, pa1.y, 0x5410), __byte_perm(pa1.z, pa1.w, 0x5410));
        sts64(base + 6144 +  (ar0 + 64) * 48 + au * 8, __byte_perm(pa1.x, pa1.y, 0x7632), __byte_perm(pa1.z, pa1.w, 0x7632));
        sts64(base + 12288 + br0 * 48 + au * 8,        __byte_perm(pb.x, pb.y, 0x5410),   __byte_perm(pb.z, pb.w, 0x5410));
        sts64(base + 15360 + br0 * 48 + au * 8,        __byte_perm(pb.x, pb.y, 0x7632),   __byte_perm(pb.z, pb.w, 0x7632));
    }
    if (tid < 64) { s_sum[tid] = 0.f; s_sq[tid] = 0.f; }
    __syncthreads();

    uint32_t aoff = (uint32_t)((wm * 32 + (lane >> 2)) * 48 + (lane & 3) * 4);
    uint32_t boff = (uint32_t)((wn * 32 + (lane >> 2)) * 48 + (lane & 3) * 4);

    for (int kt = 0; kt < NKT; kt++) {
        int b = kt & 1;
        if (kt < NKT - 1) {
            int kc = (kt + 1) * 4 + au;
            pa0 = (m0 + ar0      < M) ? AG[(size_t)(m0 + ar0)      * U4A + kc] : make_uint4(0,0,0,0);
            pa1 = (m0 + ar0 + 64 < M) ? AG[(size_t)(m0 + ar0 + 64) * U4A + kc] : make_uint4(0,0,0,0);
            pb  = WG[(size_t)(n0 + br0) * U4A + kc];
        }
        {
            uint32_t base = sb + b * SBUF;
            uint32_t AH = base + aoff, AL = base + 6144 + aoff;
            uint32_t BH = base + 12288 + boff, BL = base + 15360 + boff;
            uint32_t af[2][2][4], bfr[4][2][2];
            #pragma unroll
            for (int mt = 0; mt < 2; mt++) {
                uint32_t r = AH + mt * 16 * 48;
                af[mt][0][0] = lds32(r);            af[mt][0][1] = lds32(r + 8 * 48);
                af[mt][0][2] = lds32(r + 16);       af[mt][0][3] = lds32(r + 8 * 48 + 16);
                uint32_t q = AL + mt * 16 * 48;
                af[mt][1][0] = lds32(q);            af[mt][1][1] = lds32(q + 8 * 48);
                af[mt][1][2] = lds32(q + 16);       af[mt][1][3] = lds32(q + 8 * 48 + 16);
            }
            #pragma unroll
            for (int nt = 0; nt < 4; nt++) {
                uint32_t r = BH + nt * 8 * 48;
                bfr[nt][0][0] = lds32(r);  bfr[nt][0][1] = lds32(r + 16);
                uint32_t q = BL + nt * 8 * 48;
                bfr[nt][1][0] = lds32(q);  bfr[nt][1][1] = lds32(q + 16);
            }
            #pragma unroll
            for (int mt = 0; mt < 2; mt++)
                #pragma unroll
                for (int nt = 0; nt < 4; nt++) {
                    mma_bf16(acc[mt][nt], af[mt][0], bfr[nt][0]);
                    mma_bf16(acc[mt][nt], af[mt][0], bfr[nt][1]);
                    mma_bf16(acc[mt][nt], af[mt][1], bfr[nt][0]);
                }
        }
        if (kt < NKT - 1) {
            uint32_t base = sb + (b ^ 1) * SBUF;
            sts64(base +         ar0 * 48 + au * 8,        __byte_perm(pa0.x, pa0.y, 0x5410), __byte_perm(pa0.z, pa0.w, 0x5410));
            sts64(base + 6144 +  ar0 * 48 + au * 8,        __byte_perm(pa0.x, pa0.y, 0x7632), __byte_perm(pa0.z, pa0.w, 0x7632));
            sts64(base +         (ar0 + 64) * 48 + au * 8, __byte_perm(pa1.x, pa1.y, 0x5410), __byte_perm(pa1.z, pa1.w, 0x5410));
            sts64(base + 6144 +  (ar0 + 64) * 48 + au * 8, __byte_perm(pa1.x, pa1.y, 0x7632), __byte_perm(pa1.z, pa1.w, 0x7632));
            sts64(base + 12288 + br0 * 48 + au * 8,        __byte_perm(pb.x, pb.y, 0x5410),   __byte_perm(pb.z, pb.w, 0x5410));
            sts64(base + 15360 + br0 * 48 + au * 8,        __byte_perm(pb.x, pb.y, 0x7632),   __byte_perm(pb.z, pb.w, 0x7632));
        }
        __syncthreads();
    }

    // ---- epilogue: C + bias + s[row] -> g_h ; fused column stats ----
    float ls[4][2] = {}, lq[4][2] = {};
    #pragma unroll
    for (int mt = 0; mt < 2; mt++) {
        int row0 = m0 + wm * 32 + mt * 16 + (lane >> 2);
        int row1 = row0 + 8;
        float s0 = (row0 < M) ? g_s[row0] : 0.f;
        float s1 = (row1 < M) ? g_s[row1] : 0.f;
        #pragma unroll
        for (int nt = 0; nt < 4; nt++) {
            int col = n0 + wn * 32 + nt * 8 + (lane & 3) * 2;
            if (col < EMBC) {
                float b0 = bias[col], b1 = bias[col + 1];
                if (row0 < M) {
                    float v0 = acc[mt][nt][0] + b0 + s0;
                    float v1 = acc[mt][nt][1] + b1 + s0;
                    g_h[(size_t)row0 * EMBC + col]     = v0;
                    g_h[(size_t)row0 * EMBC + col + 1] = v1;
                    ls[nt][0] += v0; lq[nt][0] += v0 * v0;
                    ls[nt][1] += v1; lq[nt][1] += v1 * v1;
                }
                if (row1 < M) {
                    float v0 = acc[mt][nt][2] + b0 + s1;
                    float v1 = acc[mt][nt][3] + b1 + s1;
                    g_h[(size_t)row1 * EMBC + col]     = v0;
                    g_h[(size_t)row1 * EMBC + col + 1] = v1;
                    ls[nt][0] += v0; lq[nt][0] += v0 * v0;
                    ls[nt][1] += v1; lq[nt][1] += v1 * v1;
                }
            }
        }
    }
    #pragma unroll
    for (int nt = 0; nt < 4; nt++)
        #pragma unroll
        for (int jj = 0; jj < 2; jj++) {
            #pragma unroll
            for (int o = 4; o < 32; o <<= 1) {
                ls[nt][jj] += __shfl_xor_sync(0xffffffffu, ls[nt][jj], o);
                lq[nt][jj] += __shfl_xor_sync(0xffffffffu, lq[nt][jj], o);
            }
        }
    if (lane < 4) {
        #pragma unroll
        for (int nt = 0; nt < 4; nt++)
            #pragma unroll
            for (int jj = 0; jj < 2; jj++) {
                int ci = wn * 32 + nt * 8 + lane * 2 + jj;
                atomicAdd(&s_sum[ci], ls[nt][jj]);
                atomicAdd(&s_sq[ci],  lq[nt][jj]);
            }
    }
    __syncthreads();
    if (tid < 64) {
        int col = n0 + tid;
        if (col < EMBC) {
            atomicAdd(&g_colsum[col],   s_sum[tid]);
            atomicAdd(&g_colsumsq[col], s_sq[tid]);
        }
    }
}

// ================= final-layer norm (no relu), in place ================
__global__ void k_normfinal(int n)
{
    int idx = blockIdx.x * blockDim.x + threadIdx.x;
    if (idx >= n * F4) return;
    int f = (idx % F4) * 4;
    float4 sc = *(const float4*)&g_scale[f];
    float4 sh = *(const float4*)&g_shift[f];
    float4 x = ((float4*)g_h)[idx];
    ((float4*)g_h)[idx] = make_float4(fmaf(x.x, sc.x, sh.x), fmaf(x.y, sc.y, sh.y),
                                      fmaf(x.z, sc.z, sh.z), fmaf(x.w, sc.w, sh.w));
}

// ================= mean pool =================
__device__ __forceinline__ int lower_bound_i(const int* a, int n, int v)
{
    int lo = 0, hi = n;
    while (lo < hi) { int m = (lo + hi) >> 1; if (a[m] < v) lo = m + 1; else hi = m; }
    return lo;
}
__global__ void k_pool(const int* __restrict__ batch, int n)
{
    int g = blockIdx.x;
    int start = lower_bound_i(batch, n, g);
    int end   = lower_bound_i(batch, n, g + 1);
    int f = threadIdx.x;
    if (f >= EMBC) return;
    float s = 0.f;
    for (int i = start; i < end; i++)
        s += g_h[(size_t)i * EMBC + f];
    g_hg[(size_t)g * EMBC + f] = s / fmaxf((float)(end - start), 1.f);
}

// ================= SIMT sgemm for head =================
template<int EPI>
__global__ __launch_bounds__(256)
void k_sgemm(int a_sel, float* a_ext, const float* __restrict__ B,
             int c_sel, float* c_ext, int M, int N, int K,
             const float* __restrict__ bias)
{
    const float* A = sel_ptr(a_sel, a_ext);
    float*       C = sel_ptr(c_sel, c_ext);
    __shared__ __align__(16) float As[16][64];
    __shared__ __align__(16) float Bs[16][64];
    int tid = threadIdx.x;
    int tx = tid & 15, ty = tid >> 4;
    int m0 = blockIdx.x * 64, n0 = blockIdx.y * 64;
    int am = tid >> 2, ak4 = tid & 3;
    int bk = tid >> 4, bn4 = tid & 15;
    float acc[4][4] = {};
    for (int kt = 0; kt < K; kt += 16) {
        float4 av = make_float4(0.f, 0.f, 0.f, 0.f);
        int arow = m0 + am, acol = kt + ak4 * 4;
        if (arow < M && acol + 4 <= K)
            av = *(const float4*)(A + (size_t)arow * K + acol);
        As[ak4 * 4 + 0][am] = av.x;
        As[ak4 * 4 + 1][am] = av.y;
        As[ak4 * 4 + 2][am] = av.z;
        As[ak4 * 4 + 3][am] = av.w;
        float4 bv = make_float4(0.f, 0.f, 0.f, 0.f);
        int brow = kt + bk, bcol = n0 + bn4 * 4;
        if (brow < K && bcol + 4 <= N)
            bv = *(const float4*)(B + (size_t)brow * N + bcol);
        *(float4*)&Bs[bk][bn4 * 4] = bv;
        __syncthreads();
        #pragma unroll
        for (int k = 0; k < 16; k++) {
            float4 a4 = *(const float4*)&As[k][ty * 4];
            float4 b4 = *(const float4*)&Bs[k][tx * 4];
            float ar[4] = {a4.x, a4.y, a4.z, a4.w};
            float br[4] = {b4.x, b4.y, b4.z, b4.w};
            #pragma unroll
            for (int i = 0; i < 4; i++)
                #pragma unroll
                for (int j = 0; j < 4; j++)
                    acc[i][j] += ar[i] * br[j];
        }
        __syncthreads();
    }
    float bb[4];
    #pragma unroll
    for (int j = 0; j < 4; j++) {
        int col = n0 + tx * 4 + j;
        bb[j] = (col < N) ? bias[col] : 0.f;
    }
    #pragma unroll
    for (int i = 0; i < 4; i++) {
        int row = m0 + ty * 4 + i;
        if (row >= M) continue;
        #pragma unroll
        for (int j = 0; j < 4; j++) {
            int col = n0 + tx * 4 + j;
            if (col >= N) continue;
            float v = acc[i][j] + bb[j];
            if (EPI == 1)
                v = (v > 0.f) ? v + log1pf(expf(-v)) : log1pf(expf(v));
            C[(size_t)row * N + col] = v;
        }
    }
}

__global__ void k_pred(const float* __restrict__ W2, const float* __restrict__ b2,
                       float* __restrict__ out)
{
    int g = blockIdx.x;
    int w = threadIdx.x >> 5;
    int lane = threadIdx.x & 31;
    float s = 0.f;
    #pragma unroll
    for (int q = 0; q < 4; q++) {
        int i = lane * 4 + q;
        s += g_t[(size_t)g * 128 + i] * W2[i * 2 + w];
    }
    #pragma unroll
    for (int o = 16; o > 0; o >>= 1) s += __shfl_xor_sync(0xffffffffu, s, o);
    if (lane == 0) out[g * 2 + w] = s + b2[w];
}

// ======================================================================
extern "C" void kernel_launch(void* const* d_in, const int* in_sizes, int n_in,
                              void* d_out, int out_size)
{
    const int*   atom_type = (const int*)d_in[0];
    const int*   chirality = (const int*)d_in[1];
    const int*   edge_index= (const int*)d_in[2];
    const int*   edge_type = (const int*)d_in[3];
    const int*   edge_dir  = (const int*)d_in[4];
    const int*   batch     = (const int*)d_in[5];
    const float* atom_emb1 = (const float*)d_in[6];
    const float* atom_emb2 = (const float*)d_in[7];
    const float* W         = (const float*)d_in[8];
    const float* b         = (const float*)d_in[9];
    const float* ee1       = (const float*)d_in[10];
    const float* ee2       = (const float*)d_in[11];
    const float* bn_gamma  = (const float*)d_in[12];
    const float* bn_beta   = (const float*)d_in[13];
    const float* feat_W    = (const float*)d_in[14];
    const float* feat_b    = (const float*)d_in[15];
    const float* head_W1   = (const float*)d_in[16];
    const float* head_b1   = (const float*)d_in[17];
    const float* head_W2   = (const float*)d_in[18];
    const float* head_b2   = (const float*)d_in[19];

    int N  = in_sizes[0];
    int E  = in_sizes[3];
    int NG = out_size / (256 + 2);

    float* out_f = (float*)d_out;
    float* hf    = out_f;
    float* pred  = out_f + (size_t)NG * 256;

    // CSR build
    k_zero2<<<(N + 255) / 256, 256>>>(N);
    k_count<<<(E + 255) / 256, 256>>>(edge_index, E);
    k_scan<<<1, 1024>>>(N);
    k_fill<<<(E + 255) / 256, 256>>>(edge_index, edge_type, edge_dir, E);

    // embedding init (fp32 h)
    k_init<<<(N * F4 + 255) / 256, 256>>>(atom_type, chirality, atom_emb1, atom_emb2, N);

    dim3 ggrid(NPAD / 64, (N + 127) / 128);   // nb fastest -> A-tile L2 reuse
    for (int l = 0; l < NLAYER; l++) {
        const float* Wl   = W  + (size_t)l * EMBC * EMBC;
        const float* bl   = b  + (size_t)l * EMBC;
        const float* ee1l = ee1 + l * 5;
        const float* ee2l = ee2 + l * 3;

        if (l > 0)
            k_mkscale<<<2, 160>>>(bn_gamma + (l - 1) * EMBC, bn_beta + (l - 1) * EMBC, N);
        k_sconst<<<(N + 255) / 256, 256>>>(ee1l, ee2l, N);
        k_wprep<<<(NPAD * U4A + 255) / 256, 256>>>(Wl);
        k_gather2<<<(N * U4A + 255) / 256, 256>>>(N, l > 0 ? 1 : 0);
        k_gemm_mma<<<ggrid, 256>>>(bl, N);
    }

    k_mkscale<<<2, 160>>>(bn_gamma + (NLAYER - 1) * EMBC, bn_beta + (NLAYER - 1) * EMBC, N);
    k_normfinal<<<(N * F4 + 255) / 256, 256>>>(N);

    k_pool<<<NG, 320>>>(batch, N);
    {
        dim3 grid((NG + 63) / 64, (256 + 63) / 64);
        k_sgemm<0><<<grid, 256>>>(SEL_HG, nullptr, feat_W, SEL_EXT, hf,
                                  NG, 256, EMBC, feat_b);
    }
    {
        dim3 grid((NG + 63) / 64, (128 + 63) / 64);
        k_sgemm<1><<<grid, 256>>>(SEL_EXT, hf, head_W1, SEL_T, nullptr,
                                  NG, 128, 256, head_b1);
    }
    k_pred<<<NG, 64>>>(head_W2, head_b2, pred);
}